// round 14
// baseline (speedup 1.0000x reference)
#include <cuda_runtime.h>
#include <cuda_bf16.h>
#include <math.h>

#define MROWS 8192
#define NCOLS 4096
#define T_ITERS 40
#define NBLK 256               // matvec blocks
#define RPB 32                 // rows per matvec block
#define NCHUNK 32              // 1 row per chunk
#define CHUNK_BYTES NCOLS              // 4KB (int8 row)
#define CHUNK_U4 (CHUNK_BYTES / 16)    // 256 uint4
#define NBUF 12
#define PF 10                  // chunks in flight
#define REDB 64                // reducer slots (last arrivals) = norm partials
#define SMEM_BYTES (NBUF * CHUNK_BYTES)  // 48KB

// ---------------- device scratch ----------------
__device__ uint4 g_Xq[(size_t)MROWS * NCOLS / 16];  // 33.5MB int8 X
__device__ float g_sc2[MROWS];                      // per-row scale^2
__device__ float g_y[3 * NCOLS];
__device__ float g_wpart[NBLK * NCOLS];
__device__ float g_dot[NBLK];
__device__ float g_ss[(T_ITERS + 1) * REDB];
__device__ float g_alpha[T_ITERS];
__device__ int   g_ctr[T_ITERS];

// ---------------- one-time fp32 -> int8 (per-row scale) ----------------
__device__ __forceinline__ unsigned pack4(float4 f, float inv) {
    int i0 = __float2int_rn(f.x * inv);
    int i1 = __float2int_rn(f.y * inv);
    int i2 = __float2int_rn(f.z * inv);
    int i3 = __float2int_rn(f.w * inv);
    return (i0 & 255) | ((i1 & 255) << 8) | ((i2 & 255) << 16) | ((i3 & 255) << 24);
}

__global__ void __launch_bounds__(256) k_toint8(const float* __restrict__ X) {
    __shared__ float rm[256];
    int row = blockIdx.x, t = threadIdx.x;
    const float4* xr = (const float4*)(X + (size_t)row * NCOLS);
    float4 a0 = xr[4 * t + 0], a1 = xr[4 * t + 1], a2 = xr[4 * t + 2], a3 = xr[4 * t + 3];
    float m = fmaxf(fmaxf(fmaxf(fabsf(a0.x), fabsf(a0.y)), fmaxf(fabsf(a0.z), fabsf(a0.w))),
                    fmaxf(fmaxf(fabsf(a1.x), fabsf(a1.y)), fmaxf(fabsf(a1.z), fabsf(a1.w))));
    m = fmaxf(m, fmaxf(fmaxf(fabsf(a2.x), fabsf(a2.y)), fmaxf(fabsf(a2.z), fabsf(a2.w))));
    m = fmaxf(m, fmaxf(fmaxf(fabsf(a3.x), fabsf(a3.y)), fmaxf(fabsf(a3.z), fabsf(a3.w))));
    rm[t] = m;
    __syncthreads();
    for (int s = 128; s > 0; s >>= 1) {
        if (t < s) rm[t] = fmaxf(rm[t], rm[t + s]);
        __syncthreads();
    }
    float maxv = rm[0];
    float inv = 127.f / maxv;
    uint4 o;
    o.x = pack4(a0, inv); o.y = pack4(a1, inv);
    o.z = pack4(a2, inv); o.w = pack4(a3, inv);
    g_Xq[(size_t)row * 256 + t] = o;
    if (t == 0) {
        float sc = maxv * (1.0f / 127.f);
        g_sc2[row] = sc * sc;
    }
}

// ---------------- init: deterministic pseudo-random unit vector ----------------
__global__ void k_init() {
    __shared__ float red[1024];
    int t = threadIdx.x;
    float vals[4];
    float ss = 0.f;
#pragma unroll
    for (int i = 0; i < 4; i++) {
        int j = t + i * 1024;
        unsigned h = (unsigned)j * 2654435761u;
        h ^= h >> 16; h *= 2246822519u; h ^= h >> 13;
        float x = (float)(h & 0xFFFFFF) * (1.0f / 16777216.0f) - 0.5f;
        vals[i] = x;
        ss += x * x;
    }
    red[t] = ss;
    __syncthreads();
    for (int s = 512; s > 0; s >>= 1) {
        if (t < s) red[t] += red[t + s];
        __syncthreads();
    }
    float inv = rsqrtf(red[0]);
#pragma unroll
    for (int i = 0; i < 4; i++) {
        int j = t + i * 1024;
        g_y[j] = vals[i] * inv;
        g_y[2 * NCOLS + j] = 0.f;
    }
    if (t < T_ITERS) g_ctr[t] = 0;
    if (t == 0) {
        for (int p = 0; p < REDB; p++) g_ss[p] = (p == 0) ? 1.f : 0.f;
    }
}

// ---------------- fused matvec + last-arrivals reduce ----------------
__device__ __forceinline__ void prefetch_chunk(void* x_s, int slot, const uint4* src, int t) {
    unsigned base = (unsigned)__cvta_generic_to_shared((char*)x_s + slot * CHUNK_BYTES) + t * 16;
    asm volatile("cp.async.cg.shared.global [%0], [%1], 16;\n"
                 :: "r"(base), "l"(src + t) : "memory");
    asm volatile("cp.async.commit_group;\n" ::: "memory");
}

#define CV(w, j) ((float)((signed char)((w) >> (8 * (j)))))

__device__ __forceinline__ float wdot(unsigned xw, float4 v) {
    return CV(xw, 0) * v.x + CV(xw, 1) * v.y + CV(xw, 2) * v.z + CV(xw, 3) * v.w;
}

extern __shared__ uint4 x_s[];

__global__ void __launch_bounds__(256, 3) k_matvec(int it) {
    __shared__ float upart[2][8];
    __shared__ float red[256];
    __shared__ float s_invn;
    __shared__ float s_s2[RPB];
    __shared__ int s_ticket;
    __shared__ float4 sp[16][16];
    __shared__ float s_scal[4];
    int t = threadIdx.x, b = blockIdx.x;
    int lane = t & 31, w = t >> 5;

    const float4* yv = (const float4*)(g_y + (it % 3) * NCOLS);
    const uint4* Xb = g_Xq + (size_t)b * RPB * CHUNK_U4;

    float acc[16];
#pragma unroll
    for (int i = 0; i < 16; i++) acc[i] = 0.f;

    // prologue: PF chunks in flight
#pragma unroll
    for (int c = 0; c < PF; c++) prefetch_chunk(x_s, c, Xb + (size_t)c * CHUNK_U4, t);

    // invn + row scales (overlapped with prefetch latency)
    if (w == 0) {
        const float* sb = g_ss + it * REDB;
        float s = sb[lane] + sb[lane + 32];
#pragma unroll
        for (int o = 16; o > 0; o >>= 1) s += __shfl_down_sync(0xffffffffu, s, o);
        if (lane == 0) s_invn = rsqrtf(s);
    }
    if (t < RPB) s_s2[t] = g_sc2[b * RPB + t];

    asm volatile("cp.async.wait_group %0;\n" :: "n"(PF - 1) : "memory");
    __syncthreads();
    float invn = s_invn;
    {
        uint4 xb = x_s[t];
        float a0 = wdot(xb.x, __ldg(&yv[4 * t + 0])) + wdot(xb.y, __ldg(&yv[4 * t + 1]))
                 + wdot(xb.z, __ldg(&yv[4 * t + 2])) + wdot(xb.w, __ldg(&yv[4 * t + 3]));
#pragma unroll
        for (int o = 16; o > 0; o >>= 1) a0 += __shfl_down_sync(0xffffffffu, a0, o);
        if (lane == 0) upart[0][w] = a0;
    }

    for (int k = 0; k < NCHUNK; k++) {
        if (k + 1 < NCHUNK) {
            if (k + PF - 1 < NCHUNK) {
                asm volatile("cp.async.wait_group %0;\n" :: "n"(PF - 2) : "memory");
            } else {
                asm volatile("cp.async.wait_group 0;\n" ::: "memory");
            }
        }
        __syncthreads();   // chunk k+1 + upart[k&1] visible

        if (k + PF < NCHUNK)
            prefetch_chunk(x_s, (k + PF) % NBUF, Xb + (size_t)(k + PF) * CHUNK_U4, t);

        if (k + 1 < NCHUNK) {
            uint4 xb = x_s[((k + 1) % NBUF) * CHUNK_U4 + t];
            float a0 = wdot(xb.x, __ldg(&yv[4 * t + 0])) + wdot(xb.y, __ldg(&yv[4 * t + 1]))
                     + wdot(xb.z, __ldg(&yv[4 * t + 2])) + wdot(xb.w, __ldg(&yv[4 * t + 3]));
#pragma unroll
            for (int o = 16; o > 0; o >>= 1) a0 += __shfl_down_sync(0xffffffffu, a0, o);
            if (lane == 0) upart[(k + 1) & 1][w] = a0;
        }

        // phase2(row k): acc += q_row * (invn * scale^2 * dot)
        {
            const float* up = upart[k & 1];
            float u0 = invn * s_s2[k] * (((up[0] + up[1]) + (up[2] + up[3]))
                                       + ((up[4] + up[5]) + (up[6] + up[7])));
            uint4 xb = x_s[(k % NBUF) * CHUNK_U4 + t];
#pragma unroll
            for (int jw = 0; jw < 4; jw++) {
                unsigned xw = (&xb.x)[jw];
                acc[4 * jw + 0] += CV(xw, 0) * u0;
                acc[4 * jw + 1] += CV(xw, 1) * u0;
                acc[4 * jw + 2] += CV(xw, 2) * u0;
                acc[4 * jw + 3] += CV(xw, 3) * u0;
            }
        }
    }

    // epilogue: write w partials (cols 16t..16t+15) + alpha partial
    float d = 0.f;
    float4* wp = (float4*)(g_wpart + (size_t)b * NCOLS);
#pragma unroll
    for (int j = 0; j < 4; j++) {
        float4 av = make_float4(acc[4 * j + 0], acc[4 * j + 1],
                                acc[4 * j + 2], acc[4 * j + 3]);
        wp[4 * t + j] = av;
        float4 vv = __ldg(&yv[4 * t + j]);
        d += av.x * vv.x + av.y * vv.y + av.z * vv.z + av.w * vv.w;
    }
    red[t] = d;
    __syncthreads();
    for (int s = 128; s > 0; s >>= 1) {
        if (t < s) red[t] += red[t + s];
        __syncthreads();
    }
    if (t == 0) g_dot[b] = red[0] * invn;

    // ---- publish and take ticket ----
    __threadfence();
    __syncthreads();
    if (t == 0) s_ticket = atomicAdd(&g_ctr[it], 1);
    __syncthreads();
    int ticket = s_ticket;
    if (ticket < NBLK - REDB) return;
    int rb = ticket - (NBLK - REDB);

    if (t == 0) {
        while (atomicAdd(&g_ctr[it], 0) < NBLK) { }
    }
    __syncthreads();
    __threadfence();

    // ---- reduce 64 columns (16 float4 groups) for this slot ----
    int cgl = t & 15;
    int slice = t >> 4;
    int cg = rb * 16 + cgl;
    float4 wsum = make_float4(0.f, 0.f, 0.f, 0.f);
    {
        const float4* wpr = (const float4*)g_wpart + cg;
#pragma unroll
        for (int i = 0; i < 16; i++) {
            float4 v = wpr[(size_t)(slice * 16 + i) * (NCOLS / 4)];
            wsum.x += v.x; wsum.y += v.y; wsum.z += v.z; wsum.w += v.w;
        }
    }
    sp[slice][cgl] = wsum;

    if (w == 0) {
        float dv = 0.f;
#pragma unroll
        for (int i = 0; i < 8; i++) dv += g_dot[lane + 32 * i];
#pragma unroll
        for (int o = 16; o > 0; o >>= 1) dv += __shfl_down_sync(0xffffffffu, dv, o);
        if (lane == 0) s_scal[0] = dv;
    } else if (w == 1) {
        const float* sb = g_ss + it * REDB;
        float nv = sb[lane] + sb[lane + 32];
#pragma unroll
        for (int o = 16; o > 0; o >>= 1) nv += __shfl_down_sync(0xffffffffu, nv, o);
        if (lane == 0) s_scal[1] = nv;
    } else if (w == 2) {
        float nv = 0.f;
        if (it > 0) {
            const float* sb = g_ss + (it - 1) * REDB;
            nv = sb[lane] + sb[lane + 32];
        }
#pragma unroll
        for (int o = 16; o > 0; o >>= 1) nv += __shfl_down_sync(0xffffffffu, nv, o);
        if (lane == 0) s_scal[2] = nv;
    }
    __syncthreads();

    for (int s = 8; s > 0; s >>= 1) {
        if (slice < s) {
            float4 o = sp[slice + s][cgl];
            sp[slice][cgl].x += o.x; sp[slice][cgl].y += o.y;
            sp[slice][cgl].z += o.z; sp[slice][cgl].w += o.w;
        }
        __syncthreads();
    }

    if (t < 16) {
        float alpha = s_scal[0];
        float n = sqrtf(s_scal[1]);
        float ca = alpha / n;
        float cb = (it > 0) ? n * rsqrtf(s_scal[2]) : 0.f;

        float4 wv = sp[0][cgl];
        const float4* ycur = (const float4*)(g_y + (it % 3) * NCOLS);
        const float4* yprv = (const float4*)(g_y + ((it + 2) % 3) * NCOLS);
        float4* ynxt = (float4*)(g_y + ((it + 1) % 3) * NCOLS);
        float4 vc = ycur[cg], vp4 = yprv[cg];
        float4 yt;
        yt.x = wv.x - ca * vc.x - cb * vp4.x;
        yt.y = wv.y - ca * vc.y - cb * vp4.y;
        yt.z = wv.z - ca * vc.z - cb * vp4.z;
        yt.w = wv.w - ca * vc.w - cb * vp4.w;
        ynxt[cg] = yt;

        float nrm = yt.x * yt.x + yt.y * yt.y + yt.z * yt.z + yt.w * yt.w;
#pragma unroll
        for (int o = 8; o > 0; o >>= 1) nrm += __shfl_down_sync(0x0000ffffu, nrm, o);
        if (cgl == 0) {
            g_ss[(it + 1) * REDB + rb] = nrm;
            if (rb == 0) g_alpha[it] = alpha;
        }
    }
}

// ---------------- lambda_max of tridiagonal: fp32 warp-parallel Sturm bisection ----------------
__global__ void k_tridiag(float* out) {
    __shared__ float a[T_ITERS], b2[T_ITERS];
    int lane = threadIdx.x;
    for (int i = lane; i < T_ITERS; i += 32) {
        a[i] = g_alpha[i];
        float s = 0.f;
        if (i > 0) {
            for (int p = 0; p < REDB; p++) s += g_ss[i * REDB + p];
        }
        b2[i] = s;
    }
    __syncwarp();

    float lo = 1e30f, hi = -1e30f;
    for (int i = lane; i < T_ITERS; i += 32) {
        float r = sqrtf(b2[i]) + ((i + 1 < T_ITERS) ? sqrtf(b2[i + 1]) : 0.f);
        lo = fminf(lo, a[i] - r);
        hi = fmaxf(hi, a[i] + r);
    }
#pragma unroll
    for (int o = 16; o > 0; o >>= 1) {
        lo = fminf(lo, __shfl_xor_sync(0xffffffffu, lo, o));
        hi = fmaxf(hi, __shfl_xor_sync(0xffffffffu, hi, o));
    }
    lo -= 1.f; hi += 1.f;

    for (int round = 0; round < 6; round++) {
        float wdt = (hi - lo) * (1.0f / 33.0f);
        float x = lo + wdt * (float)(lane + 1);
        int cnt = 0;
        float d = a[0] - x;
        if (d == 0.f) d = -1e-30f;
        if (d < 0.f) cnt++;
#pragma unroll 4
        for (int i = 1; i < T_ITERS; i++) {
            d = a[i] - x - __fdividef(b2[i], d);
            if (d == 0.f) d = -1e-30f;
            if (d < 0.f) cnt++;
        }
        unsigned m = __ballot_sync(0xffffffffu, cnt >= T_ITERS);
        if (m) {
            int f = __ffs(m) - 1;
            hi = lo + wdt * (float)(f + 1);
            lo = lo + wdt * (float)f;
        } else {
            lo = lo + wdt * 32.f;
        }
    }
    if (lane == 0) out[0] = 0.5f * (lo + hi);
}

// ---------------- launch ----------------
extern "C" void kernel_launch(void* const* d_in, const int* in_sizes, int n_in,
                              void* d_out, int out_size) {
    const float* X = (const float*)d_in[0];
    float* out = (float*)d_out;

    cudaFuncSetAttribute(k_matvec, cudaFuncAttributeMaxDynamicSharedMemorySize, SMEM_BYTES);

    k_toint8<<<MROWS, 256>>>(X);
    k_init<<<1, 1024>>>();
    for (int it = 0; it < T_ITERS; it++) {
        k_matvec<<<NBLK, 256, SMEM_BYTES>>>(it);
    }
    k_tridiag<<<1, 32>>>(out);
}

// round 15
// speedup vs baseline: 1.8302x; 1.8302x over previous
#include <cuda_runtime.h>
#include <math.h>

#define MROWS 8192
#define NCOLS 4096
#define T_ITERS 36
#define NBLK 256               // matvec blocks
#define RPB 32                 // rows per matvec block
#define NCHUNK 32              // 1 row per chunk
#define CHUNK_BYTES NCOLS              // 4KB (int8 row)
#define CHUNK_U4 (CHUNK_BYTES / 16)    // 256 uint4
#define NBUF 12
#define PF 10                  // chunks in flight
#define REDB 64                // reducer slots (last arrivals) = norm partials
#define SMEM_BYTES (NBUF * CHUNK_BYTES)  // 48KB
#define MAGIC 8388736.0f       // 2^23 + 128 (biased-byte magic)

// ---------------- device scratch ----------------
__device__ uint4 g_Xq[(size_t)MROWS * NCOLS / 16];  // 33.5MB biased-int8 X
__device__ float g_sc2[MROWS];                      // per-row scale^2
__device__ float g_y[3 * NCOLS];
__device__ float g_wpart[NBLK * NCOLS];
__device__ float g_dot[NBLK];
__device__ float g_ss[(T_ITERS + 1) * REDB];
__device__ float g_alpha[T_ITERS];
__device__ int   g_ctr[T_ITERS];

// ---------------- one-time fp32 -> biased int8 (per-row scale) ----------------
__device__ __forceinline__ unsigned pack4b(float4 f, float inv) {
    int i0 = __float2int_rn(f.x * inv) + 128;
    int i1 = __float2int_rn(f.y * inv) + 128;
    int i2 = __float2int_rn(f.z * inv) + 128;
    int i3 = __float2int_rn(f.w * inv) + 128;
    return (i0 & 255) | ((i1 & 255) << 8) | ((i2 & 255) << 16) | ((i3 & 255) << 24);
}

__global__ void __launch_bounds__(256) k_toint8(const float* __restrict__ X) {
    __shared__ float rm[256];
    int row = blockIdx.x, t = threadIdx.x;
    const float4* xr = (const float4*)(X + (size_t)row * NCOLS);
    float4 a0 = xr[4 * t + 0], a1 = xr[4 * t + 1], a2 = xr[4 * t + 2], a3 = xr[4 * t + 3];
    float m = fmaxf(fmaxf(fmaxf(fabsf(a0.x), fabsf(a0.y)), fmaxf(fabsf(a0.z), fabsf(a0.w))),
                    fmaxf(fmaxf(fabsf(a1.x), fabsf(a1.y)), fmaxf(fabsf(a1.z), fabsf(a1.w))));
    m = fmaxf(m, fmaxf(fmaxf(fabsf(a2.x), fabsf(a2.y)), fmaxf(fabsf(a2.z), fabsf(a2.w))));
    m = fmaxf(m, fmaxf(fmaxf(fabsf(a3.x), fabsf(a3.y)), fmaxf(fabsf(a3.z), fabsf(a3.w))));
    rm[t] = m;
    __syncthreads();
    for (int s = 128; s > 0; s >>= 1) {
        if (t < s) rm[t] = fmaxf(rm[t], rm[t + s]);
        __syncthreads();
    }
    float maxv = rm[0];
    float inv = 127.f / maxv;
    uint4 o;
    o.x = pack4b(a0, inv); o.y = pack4b(a1, inv);
    o.z = pack4b(a2, inv); o.w = pack4b(a3, inv);
    g_Xq[(size_t)row * 256 + t] = o;
    if (t == 0) {
        float sc = maxv * (1.0f / 127.f);
        g_sc2[row] = sc * sc;
    }
}

// ---------------- init: deterministic pseudo-random unit vector ----------------
__global__ void k_init() {
    __shared__ float red[1024];
    int t = threadIdx.x;
    float vals[4];
    float ss = 0.f;
#pragma unroll
    for (int i = 0; i < 4; i++) {
        int j = t + i * 1024;
        unsigned h = (unsigned)j * 2654435761u;
        h ^= h >> 16; h *= 2246822519u; h ^= h >> 13;
        float x = (float)(h & 0xFFFFFF) * (1.0f / 16777216.0f) - 0.5f;
        vals[i] = x;
        ss += x * x;
    }
    red[t] = ss;
    __syncthreads();
    for (int s = 512; s > 0; s >>= 1) {
        if (t < s) red[t] += red[t + s];
        __syncthreads();
    }
    float inv = rsqrtf(red[0]);
#pragma unroll
    for (int i = 0; i < 4; i++) {
        int j = t + i * 1024;
        g_y[j] = vals[i] * inv;
        g_y[2 * NCOLS + j] = 0.f;
    }
    if (t < T_ITERS) g_ctr[t] = 0;
    if (t == 0) {
        for (int p = 0; p < REDB; p++) g_ss[p] = (p == 0) ? 1.f : 0.f;
    }
}

// ---------------- fused matvec + last-arrivals reduce ----------------
__device__ __forceinline__ void prefetch_chunk(void* x_s, int slot, const uint4* src, int t) {
    unsigned base = (unsigned)__cvta_generic_to_shared((char*)x_s + slot * CHUNK_BYTES) + t * 16;
    asm volatile("cp.async.cg.shared.global [%0], [%1], 16;\n"
                 :: "r"(base), "l"(src + t) : "memory");
    asm volatile("cp.async.commit_group;\n" ::: "memory");
}

// biased byte j of xw as float (2^23 + 128 + b); bias removed algebraically by caller
#define QF(xw, j) __uint_as_float(__byte_perm((xw), 0x4B000000u, 0x7650u | (j)))

extern __shared__ uint4 x_s[];

__global__ void __launch_bounds__(256, 2) k_matvec(int it) {
    __shared__ float upart[2][8];
    __shared__ float red[256];
    __shared__ float s_invn;
    __shared__ float s_s2[RPB];
    __shared__ int s_ticket;
    __shared__ float4 sp[16][16];
    __shared__ float s_scal[4];
    int t = threadIdx.x, b = blockIdx.x;
    int lane = t & 31, w = t >> 5;

    const float4* yv = (const float4*)(g_y + (it % 3) * NCOLS);
    const uint4* Xb = g_Xq + (size_t)b * RPB * CHUNK_U4;

    // prologue: PF chunks in flight
#pragma unroll
    for (int c = 0; c < PF; c++) prefetch_chunk(x_s, c, Xb + (size_t)c * CHUNK_U4, t);

    // v in registers (cols 16t..16t+15) + vsum, loaded once per iteration
    float vr[16], vsum = 0.f;
#pragma unroll
    for (int j = 0; j < 4; j++) {
        float4 vv = __ldg(&yv[4 * t + j]);
        vr[4 * j + 0] = vv.x; vr[4 * j + 1] = vv.y;
        vr[4 * j + 2] = vv.z; vr[4 * j + 3] = vv.w;
        vsum += (vv.x + vv.y) + (vv.z + vv.w);
    }

    // invn + row scales (overlapped with prefetch latency)
    if (w == 0) {
        const float* sb = g_ss + it * REDB;
        float s = sb[lane] + sb[lane + 32];
#pragma unroll
        for (int o = 16; o > 0; o >>= 1) s += __shfl_down_sync(0xffffffffu, s, o);
        if (lane == 0) s_invn = rsqrtf(s);
    }
    if (t < RPB) s_s2[t] = g_sc2[b * RPB + t];

    float acc[16];
#pragma unroll
    for (int i = 0; i < 16; i++) acc[i] = 0.f;
    float usum = 0.f;

    asm volatile("cp.async.wait_group %0;\n" :: "n"(PF - 1) : "memory");
    __syncthreads();
    float invn = s_invn;
    {
        uint4 xb = x_s[t];
        float a0 = 0.f;
#pragma unroll
        for (int jw = 0; jw < 4; jw++) {
            unsigned xw = (&xb.x)[jw];
#pragma unroll
            for (int j = 0; j < 4; j++) a0 = fmaf(QF(xw, j), vr[4 * jw + j], a0);
        }
        a0 = fmaf(-MAGIC, vsum, a0);
#pragma unroll
        for (int o = 16; o > 0; o >>= 1) a0 += __shfl_down_sync(0xffffffffu, a0, o);
        if (lane == 0) upart[0][w] = a0;
    }

    for (int k = 0; k < NCHUNK; k++) {
        if (k + 1 < NCHUNK) {
            if (k + PF - 1 < NCHUNK) {
                asm volatile("cp.async.wait_group %0;\n" :: "n"(PF - 2) : "memory");
            } else {
                asm volatile("cp.async.wait_group 0;\n" ::: "memory");
            }
        }
        __syncthreads();   // chunk k+1 + upart[k&1] visible

        if (k + PF < NCHUNK)
            prefetch_chunk(x_s, (k + PF) % NBUF, Xb + (size_t)(k + PF) * CHUNK_U4, t);

        if (k + 1 < NCHUNK) {
            uint4 xb = x_s[((k + 1) % NBUF) * CHUNK_U4 + t];
            float a0 = 0.f;
#pragma unroll
            for (int jw = 0; jw < 4; jw++) {
                unsigned xw = (&xb.x)[jw];
#pragma unroll
                for (int j = 0; j < 4; j++) a0 = fmaf(QF(xw, j), vr[4 * jw + j], a0);
            }
            a0 = fmaf(-MAGIC, vsum, a0);
#pragma unroll
            for (int o = 16; o > 0; o >>= 1) a0 += __shfl_down_sync(0xffffffffu, a0, o);
            if (lane == 0) upart[(k + 1) & 1][w] = a0;
        }

        // phase2(row k): acc += (q_row - C) * u0, bias deferred via usum
        {
            const float* up = upart[k & 1];
            float u0 = invn * s_s2[k] * (((up[0] + up[1]) + (up[2] + up[3]))
                                       + ((up[4] + up[5]) + (up[6] + up[7])));
            usum += u0;
            uint4 xb = x_s[(k % NBUF) * CHUNK_U4 + t];
#pragma unroll
            for (int jw = 0; jw < 4; jw++) {
                unsigned xw = (&xb.x)[jw];
#pragma unroll
                for (int j = 0; j < 4; j++)
                    acc[4 * jw + j] = fmaf(QF(xw, j), u0, acc[4 * jw + j]);
            }
        }
    }

    // remove deferred bias: acc_j -= C * sum(u0)
#pragma unroll
    for (int i = 0; i < 16; i++) acc[i] = fmaf(-MAGIC, usum, acc[i]);

    // epilogue: write w partials (cols 16t..16t+15) + alpha partial
    float d = 0.f;
    float4* wp = (float4*)(g_wpart + (size_t)b * NCOLS);
#pragma unroll
    for (int j = 0; j < 4; j++) {
        float4 av = make_float4(acc[4 * j + 0], acc[4 * j + 1],
                                acc[4 * j + 2], acc[4 * j + 3]);
        wp[4 * t + j] = av;
        d += av.x * vr[4 * j + 0] + av.y * vr[4 * j + 1]
           + av.z * vr[4 * j + 2] + av.w * vr[4 * j + 3];
    }
    red[t] = d;
    __syncthreads();
    for (int s = 128; s > 0; s >>= 1) {
        if (t < s) red[t] += red[t + s];
        __syncthreads();
    }
    if (t == 0) g_dot[b] = red[0] * invn;

    // ---- publish and take ticket ----
    __threadfence();
    __syncthreads();
    if (t == 0) s_ticket = atomicAdd(&g_ctr[it], 1);
    __syncthreads();
    int ticket = s_ticket;
    if (ticket < NBLK - REDB) return;
    int rb = ticket - (NBLK - REDB);

    // ---- wait for all blocks (co-residency: 2 CTAs/SM x 148 = 296 >= 256) ----
    if (t == 0) {
        while (atomicAdd(&g_ctr[it], 0) < NBLK) { }
    }
    __syncthreads();
    __threadfence();

    // ---- reduce 64 columns (16 float4 groups) for this slot ----
    int cgl = t & 15;
    int slice = t >> 4;
    int cg = rb * 16 + cgl;
    float4 wsum = make_float4(0.f, 0.f, 0.f, 0.f);
    {
        const float4* wpr = (const float4*)g_wpart + cg;
#pragma unroll
        for (int i = 0; i < 16; i++) {
            float4 v = wpr[(size_t)(slice * 16 + i) * (NCOLS / 4)];
            wsum.x += v.x; wsum.y += v.y; wsum.z += v.z; wsum.w += v.w;
        }
    }
    sp[slice][cgl] = wsum;

    if (w == 0) {
        float dv = 0.f;
#pragma unroll
        for (int i = 0; i < 8; i++) dv += g_dot[lane + 32 * i];
#pragma unroll
        for (int o = 16; o > 0; o >>= 1) dv += __shfl_down_sync(0xffffffffu, dv, o);
        if (lane == 0) s_scal[0] = dv;
    } else if (w == 1) {
        const float* sb = g_ss + it * REDB;
        float nv = sb[lane] + sb[lane + 32];
#pragma unroll
        for (int o = 16; o > 0; o >>= 1) nv += __shfl_down_sync(0xffffffffu, nv, o);
        if (lane == 0) s_scal[1] = nv;
    } else if (w == 2) {
        float nv = 0.f;
        if (it > 0) {
            const float* sb = g_ss + (it - 1) * REDB;
            nv = sb[lane] + sb[lane + 32];
        }
#pragma unroll
        for (int o = 16; o > 0; o >>= 1) nv += __shfl_down_sync(0xffffffffu, nv, o);
        if (lane == 0) s_scal[2] = nv;
    }
    __syncthreads();

    for (int s = 8; s > 0; s >>= 1) {
        if (slice < s) {
            float4 o = sp[slice + s][cgl];
            sp[slice][cgl].x += o.x; sp[slice][cgl].y += o.y;
            sp[slice][cgl].z += o.z; sp[slice][cgl].w += o.w;
        }
        __syncthreads();
    }

    if (t < 16) {
        float alpha = s_scal[0];
        float n = sqrtf(s_scal[1]);
        float ca = alpha / n;
        float cb = (it > 0) ? n * rsqrtf(s_scal[2]) : 0.f;

        float4 wv = sp[0][cgl];
        const float4* ycur = (const float4*)(g_y + (it % 3) * NCOLS);
        const float4* yprv = (const float4*)(g_y + ((it + 2) % 3) * NCOLS);
        float4* ynxt = (float4*)(g_y + ((it + 1) % 3) * NCOLS);
        float4 vc = ycur[cg], vp4 = yprv[cg];
        float4 yt;
        yt.x = wv.x - ca * vc.x - cb * vp4.x;
        yt.y = wv.y - ca * vc.y - cb * vp4.y;
        yt.z = wv.z - ca * vc.z - cb * vp4.z;
        yt.w = wv.w - ca * vc.w - cb * vp4.w;
        ynxt[cg] = yt;

        float nrm = yt.x * yt.x + yt.y * yt.y + yt.z * yt.z + yt.w * yt.w;
#pragma unroll
        for (int o = 8; o > 0; o >>= 1) nrm += __shfl_down_sync(0x0000ffffu, nrm, o);
        if (cgl == 0) {
            g_ss[(it + 1) * REDB + rb] = nrm;
            if (rb == 0) g_alpha[it] = alpha;
        }
    }
}

// ---------------- lambda_max of tridiagonal: fp32 warp-parallel Sturm bisection ----------------
__global__ void k_tridiag(float* out) {
    __shared__ float a[T_ITERS], b2[T_ITERS];
    int lane = threadIdx.x;
    for (int i = lane; i < T_ITERS; i += 32) {
        a[i] = g_alpha[i];
        float s = 0.f;
        if (i > 0) {
            for (int p = 0; p < REDB; p++) s += g_ss[i * REDB + p];
        }
        b2[i] = s;
    }
    __syncwarp();

    float lo = 1e30f, hi = -1e30f;
    for (int i = lane; i < T_ITERS; i += 32) {
        float r = sqrtf(b2[i]) + ((i + 1 < T_ITERS) ? sqrtf(b2[i + 1]) : 0.f);
        lo = fminf(lo, a[i] - r);
        hi = fmaxf(hi, a[i] + r);
    }
#pragma unroll
    for (int o = 16; o > 0; o >>= 1) {
        lo = fminf(lo, __shfl_xor_sync(0xffffffffu, lo, o));
        hi = fmaxf(hi, __shfl_xor_sync(0xffffffffu, hi, o));
    }
    lo -= 1.f; hi += 1.f;

    for (int round = 0; round < 6; round++) {
        float wdt = (hi - lo) * (1.0f / 33.0f);
        float x = lo + wdt * (float)(lane + 1);
        int cnt = 0;
        float d = a[0] - x;
        if (d == 0.f) d = -1e-30f;
        if (d < 0.f) cnt++;
#pragma unroll 4
        for (int i = 1; i < T_ITERS; i++) {
            d = a[i] - x - __fdividef(b2[i], d);
            if (d == 0.f) d = -1e-30f;
            if (d < 0.f) cnt++;
        }
        unsigned m = __ballot_sync(0xffffffffu, cnt >= T_ITERS);
        if (m) {
            int f = __ffs(m) - 1;
            hi = lo + wdt * (float)(f + 1);
            lo = lo + wdt * (float)f;
        } else {
            lo = lo + wdt * 32.f;
        }
    }
    if (lane == 0) out[0] = 0.5f * (lo + hi);
}

// ---------------- launch ----------------
extern "C" void kernel_launch(void* const* d_in, const int* in_sizes, int n_in,
                              void* d_out, int out_size) {
    const float* X = (const float*)d_in[0];
    float* out = (float*)d_out;

    cudaFuncSetAttribute(k_matvec, cudaFuncAttributeMaxDynamicSharedMemorySize, SMEM_BYTES);

    k_toint8<<<MROWS, 256>>>(X);
    k_init<<<1, 1024>>>();
    for (int it = 0; it < T_ITERS; it++) {
        k_matvec<<<NBLK, 256, SMEM_BYTES>>>(it);
    }
    k_tridiag<<<1, 32>>>(out);
}